// round 5
// baseline (speedup 1.0000x reference)
#include <cuda_runtime.h>
#include <cuda_bf16.h>

#define NB    512
#define DIN   128
#define DH    256
#define COUT  0

// Packed fp32x2 FMA (Blackwell double-rate fp32). Lanes accumulate even/odd k.
#define FMA2(d, a, b) \
    asm("fma.rn.f32x2 %0, %1, %2, %0;" : "+l"(d) : "l"(a), "l"(b))

__device__ __forceinline__ float pairsum(unsigned long long v) {
    float2 u = *(float2*)&v;
    return u.x + u.y;
}

// Scratch
__device__ float g_H1[2][NB * DH];
__device__ float g_H2[2][NB * DH];
__device__ float g_D1[2][NB * DH];
__device__ float g_D2[2][NB * DH];
__device__ float g_invn[2][NB];
__device__ float g_S[5][NB * NB];   // 0:Sx 1:Sh1 2:Sh2 3:Sd1 4:Sd2

// ===========================================================================
// Feature GEMMs: 32x64 tile, KT=32 (16 k-pairs), 256 thr, micro 2x4 f32x2.
// MODE 0: H1 = relu(X @ W1 + b1)            (K=DIN)
// MODE 1: A2 = H1 @ W2 + b2 -> H2, D2       (K=DH)
// MODE 2: D1 = mask(H1) * (D2 @ W2^T)       (K=DH, W2 rows transposed on fill)
// smem layout: S[kpair][idx*2 + (k&1)]  (pair-interleaved)
// ===========================================================================
template <int MODE>
__global__ void __launch_bounds__(256)
feat_gemm(const float* __restrict__ x1, const float* __restrict__ x2,
          const float* __restrict__ W1, const float* __restrict__ b1,
          const float* __restrict__ W2, const float* __restrict__ b2,
          const float* __restrict__ W3)
{
    __shared__ alignas(16) float As[2][16][68];    // 32 rows paired
    __shared__ alignas(16) float Bs[2][16][132];   // 64 cols paired

    const int side = blockIdx.z;
    const int i0 = blockIdx.x * 32;
    const int n0 = blockIdx.y * 64;
    const int tid = threadIdx.x;
    const int ti = tid >> 4;      // rows ti*2 .. ti*2+1
    const int tj = tid & 15;      // cols tj*4 .. tj*4+3

    const float* __restrict__ Ap;
    int K, lda;
    if (MODE == 0) { Ap = side ? x2 : x1; K = DIN; lda = DIN; }
    else if (MODE == 1) { Ap = g_H1[side]; K = DH; lda = DH; }
    else { Ap = g_D2[side]; K = DH; lda = DH; }
    const int T = K / 32;

    // A fill: row = tid>>3 (0..31), k4 = tid&7 (0..7) -> one float4
    const int far = tid >> 3;
    const int fak = tid & 7;
    // B fill MODE 0/1: col4 = (tid&15)*4, keven = (tid>>4)*2
    // B fill MODE 2: idx = tid>>2 (0..63), k4 = (tid&3)+q*4, q=0..1
    float4 ra, rb0, rb1;

    auto load_tiles = [&](int t) {
        int k0 = t * 32;
        ra = *(const float4*)&Ap[(i0 + far) * lda + k0 + fak * 4];
        if (MODE == 2) {
            int idx = tid >> 2, kb = tid & 3;
            rb0 = *(const float4*)&W2[(n0 + idx) * DH + k0 + kb * 4];
            rb1 = *(const float4*)&W2[(n0 + idx) * DH + k0 + (kb + 4) * 4];
        } else {
            const float* __restrict__ Bp = (MODE == 0) ? W1 : W2;
            int col4 = (tid & 15) * 4, ke = (tid >> 4) * 2;
            rb0 = *(const float4*)&Bp[(k0 + ke) * DH + n0 + col4];
            rb1 = *(const float4*)&Bp[(k0 + ke + 1) * DH + n0 + col4];
        }
    };
    auto store_tiles = [&](int buf) {
        int kp = fak * 2;
        *(float2*)&As[buf][kp][far * 2]     = make_float2(ra.x, ra.y);
        *(float2*)&As[buf][kp + 1][far * 2] = make_float2(ra.z, ra.w);
        if (MODE == 2) {
            int idx = tid >> 2, kb = tid & 3;
            int kp0 = kb * 2, kp1 = (kb + 4) * 2;
            *(float2*)&Bs[buf][kp0][idx * 2]     = make_float2(rb0.x, rb0.y);
            *(float2*)&Bs[buf][kp0 + 1][idx * 2] = make_float2(rb0.z, rb0.w);
            *(float2*)&Bs[buf][kp1][idx * 2]     = make_float2(rb1.x, rb1.y);
            *(float2*)&Bs[buf][kp1 + 1][idx * 2] = make_float2(rb1.z, rb1.w);
        } else {
            int col4 = (tid & 15) * 4, kp2 = tid >> 4;
            *(float2*)&Bs[buf][kp2][(col4 + 0) * 2] = make_float2(rb0.x, rb1.x);
            *(float2*)&Bs[buf][kp2][(col4 + 1) * 2] = make_float2(rb0.y, rb1.y);
            *(float2*)&Bs[buf][kp2][(col4 + 2) * 2] = make_float2(rb0.z, rb1.z);
            *(float2*)&Bs[buf][kp2][(col4 + 3) * 2] = make_float2(rb0.w, rb1.w);
        }
    };

    unsigned long long acc[8] = {};

    load_tiles(0);
    store_tiles(0);
    __syncthreads();

    for (int t = 0; t < T; t++) {
        if (t + 1 < T) load_tiles(t + 1);
        int b = t & 1;
#pragma unroll
        for (int kp = 0; kp < 16; kp++) {
            ulonglong2 a  = *(const ulonglong2*)&As[b][kp][ti * 4];
            ulonglong2 b0 = *(const ulonglong2*)&Bs[b][kp][tj * 8];
            ulonglong2 b1 = *(const ulonglong2*)&Bs[b][kp][tj * 8 + 4];
            FMA2(acc[0], a.x, b0.x);
            FMA2(acc[1], a.x, b0.y);
            FMA2(acc[2], a.x, b1.x);
            FMA2(acc[3], a.x, b1.y);
            FMA2(acc[4], a.y, b0.x);
            FMA2(acc[5], a.y, b0.y);
            FMA2(acc[6], a.y, b1.x);
            FMA2(acc[7], a.y, b1.y);
        }
        if (t + 1 < T) store_tiles((t + 1) & 1);
        __syncthreads();
    }

    float r0[4], r1[4];
#pragma unroll
    for (int c = 0; c < 4; c++) { r0[c] = pairsum(acc[c]); r1[c] = pairsum(acc[4 + c]); }

    const int col = n0 + tj * 4;
    if (MODE == 0) {
        float4 bias = *(const float4*)&b1[col];
        float bv[4] = {bias.x, bias.y, bias.z, bias.w};
#pragma unroll
        for (int r = 0; r < 2; r++) {
            float* a = r ? r1 : r0;
            float4 o;
            o.x = fmaxf(a[0] + bv[0], 0.0f);
            o.y = fmaxf(a[1] + bv[1], 0.0f);
            o.z = fmaxf(a[2] + bv[2], 0.0f);
            o.w = fmaxf(a[3] + bv[3], 0.0f);
            *(float4*)&g_H1[side][(i0 + ti * 2 + r) * DH + col] = o;
        }
    } else if (MODE == 1) {
        float4 bias = *(const float4*)&b2[col];
        float bv[4] = {bias.x, bias.y, bias.z, bias.w};
        float w3c[4];
#pragma unroll
        for (int c = 0; c < 4; c++) w3c[c] = W3[(col + c) * 10 + COUT];
#pragma unroll
        for (int r = 0; r < 2; r++) {
            float* a = r ? r1 : r0;
            float4 h, d;
            float v0 = a[0] + bv[0], v1 = a[1] + bv[1];
            float v2 = a[2] + bv[2], v3 = a[3] + bv[3];
            h.x = fmaxf(v0, 0.0f); d.x = v0 > 0.0f ? w3c[0] : 0.0f;
            h.y = fmaxf(v1, 0.0f); d.y = v1 > 0.0f ? w3c[1] : 0.0f;
            h.z = fmaxf(v2, 0.0f); d.z = v2 > 0.0f ? w3c[2] : 0.0f;
            h.w = fmaxf(v3, 0.0f); d.w = v3 > 0.0f ? w3c[3] : 0.0f;
            int off = (i0 + ti * 2 + r) * DH + col;
            *(float4*)&g_H2[side][off] = h;
            *(float4*)&g_D2[side][off] = d;
        }
    } else {
#pragma unroll
        for (int r = 0; r < 2; r++) {
            float* a = r ? r1 : r0;
            int off = (i0 + ti * 2 + r) * DH + col;
            float4 h1 = *(const float4*)&g_H1[side][off];
            float4 o;
            o.x = h1.x > 0.0f ? a[0] : 0.0f;
            o.y = h1.y > 0.0f ? a[1] : 0.0f;
            o.z = h1.z > 0.0f ? a[2] : 0.0f;
            o.w = h1.w > 0.0f ? a[3] : 0.0f;
            *(float4*)&g_D1[side][off] = o;
        }
    }
}

// ===========================================================================
// Per-sample inverse norms. One warp per sample, float4 loads.
// ===========================================================================
__device__ __forceinline__ float warp_sum(float v) {
#pragma unroll
    for (int o = 16; o > 0; o >>= 1)
        v += __shfl_down_sync(0xffffffffu, v, o);
    return v;
}

__device__ __forceinline__ float sq4(float4 v) {
    return fmaf(v.x, v.x, fmaf(v.y, v.y, fmaf(v.z, v.z, v.w * v.w)));
}

__global__ void __launch_bounds__(256)
norms_kernel(const float* __restrict__ x1, const float* __restrict__ x2)
{
    const int warp = threadIdx.x >> 5;
    const int lane = threadIdx.x & 31;
    const int gs = blockIdx.x * 8 + warp;
    const int side = gs >> 9;
    const int i = gs & (NB - 1);
    const float* __restrict__ X = side ? x2 : x1;

    float sx = sq4(*(const float4*)&X[i * DIN + lane * 4]);
    const int o0 = i * DH + lane * 8;
    float sh1 = sq4(*(const float4*)&g_H1[side][o0]) + sq4(*(const float4*)&g_H1[side][o0 + 4]);
    float sh2 = sq4(*(const float4*)&g_H2[side][o0]) + sq4(*(const float4*)&g_H2[side][o0 + 4]);
    float sd1 = sq4(*(const float4*)&g_D1[side][o0]) + sq4(*(const float4*)&g_D1[side][o0 + 4]);
    float sd2 = sq4(*(const float4*)&g_D2[side][o0]) + sq4(*(const float4*)&g_D2[side][o0 + 4]);

    sx = warp_sum(sx); sh1 = warp_sum(sh1); sh2 = warp_sum(sh2);
    sd1 = warp_sum(sd1); sd2 = warp_sum(sd2);
    if (lane == 0) {
        float n2 = (1.0f + sx) * sd1 + (1.0f + sh1) * sd2 + 1.0f + sh2;
        g_invn[side][i] = rsqrtf(n2);
    }
}

// ===========================================================================
// 5 Grams (NT), 64x64 tile, KT=32, micro 4x4 f32x2, double-buffered.
// ===========================================================================
__global__ void __launch_bounds__(256)
gram_kernel(const float* __restrict__ x1, const float* __restrict__ x2)
{
    __shared__ alignas(16) float As[2][16][132];
    __shared__ alignas(16) float Bs[2][16][132];

    const int z = blockIdx.z;
    const int i0 = blockIdx.x * 64, j0 = blockIdx.y * 64;
    const int tid = threadIdx.x;
    const int ti = tid >> 4, tj = tid & 15;

    const float* A;
    const float* B;
    int K, lda;
    switch (z) {
        case 0: A = x1;       B = x2;       K = DIN; lda = DIN; break;
        case 1: A = g_H1[0];  B = g_H1[1];  K = DH;  lda = DH;  break;
        case 2: A = g_H2[0];  B = g_H2[1];  K = DH;  lda = DH;  break;
        case 3: A = g_D1[0];  B = g_D1[1];  K = DH;  lda = DH;  break;
        default:A = g_D2[0];  B = g_D2[1];  K = DH;  lda = DH;  break;
    }
    const int T = K / 32;

    const int fidx = tid >> 2;          // 0..63 (sample row within tile)
    const int fkb  = tid & 3;           // k4 base

    float4 ra[2], rb[2];
    auto load_tiles = [&](int t) {
        int k0 = t * 32;
#pragma unroll
        for (int q = 0; q < 2; q++) {
            int k4 = fkb + q * 4;
            ra[q] = *(const float4*)&A[(i0 + fidx) * lda + k0 + k4 * 4];
            rb[q] = *(const float4*)&B[(j0 + fidx) * lda + k0 + k4 * 4];
        }
    };
    auto store_tiles = [&](int buf) {
#pragma unroll
        for (int q = 0; q < 2; q++) {
            int kp = (fkb + q * 4) * 2;
            *(float2*)&As[buf][kp][fidx * 2]     = make_float2(ra[q].x, ra[q].y);
            *(float2*)&As[buf][kp + 1][fidx * 2] = make_float2(ra[q].z, ra[q].w);
            *(float2*)&Bs[buf][kp][fidx * 2]     = make_float2(rb[q].x, rb[q].y);
            *(float2*)&Bs[buf][kp + 1][fidx * 2] = make_float2(rb[q].z, rb[q].w);
        }
    };

    unsigned long long acc[16] = {};

    load_tiles(0);
    store_tiles(0);
    __syncthreads();

    for (int t = 0; t < T; t++) {
        if (t + 1 < T) load_tiles(t + 1);
        int b = t & 1;
#pragma unroll
        for (int kp = 0; kp < 16; kp++) {
            ulonglong2 a0 = *(const ulonglong2*)&As[b][kp][ti * 8];
            ulonglong2 a1 = *(const ulonglong2*)&As[b][kp][ti * 8 + 4];
            ulonglong2 b0 = *(const ulonglong2*)&Bs[b][kp][tj * 8];
            ulonglong2 b1 = *(const ulonglong2*)&Bs[b][kp][tj * 8 + 4];
            FMA2(acc[0],  a0.x, b0.x);
            FMA2(acc[1],  a0.x, b0.y);
            FMA2(acc[2],  a0.x, b1.x);
            FMA2(acc[3],  a0.x, b1.y);
            FMA2(acc[4],  a0.y, b0.x);
            FMA2(acc[5],  a0.y, b0.y);
            FMA2(acc[6],  a0.y, b1.x);
            FMA2(acc[7],  a0.y, b1.y);
            FMA2(acc[8],  a1.x, b0.x);
            FMA2(acc[9],  a1.x, b0.y);
            FMA2(acc[10], a1.x, b1.x);
            FMA2(acc[11], a1.x, b1.y);
            FMA2(acc[12], a1.y, b0.x);
            FMA2(acc[13], a1.y, b0.y);
            FMA2(acc[14], a1.y, b1.x);
            FMA2(acc[15], a1.y, b1.y);
        }
        if (t + 1 < T) store_tiles((t + 1) & 1);
        __syncthreads();
    }

#pragma unroll
    for (int r = 0; r < 4; r++) {
        float4 o;
        o.x = pairsum(acc[r * 4 + 0]);
        o.y = pairsum(acc[r * 4 + 1]);
        o.z = pairsum(acc[r * 4 + 2]);
        o.w = pairsum(acc[r * 4 + 3]);
        *(float4*)&g_S[z][(i0 + ti * 4 + r) * NB + j0 + tj * 4] = o;
    }
}

// ===========================================================================
// Elementwise combine + normalize.
// ===========================================================================
__global__ void __launch_bounds__(256)
combine_kernel(float* __restrict__ out)
{
    const int e = (blockIdx.x * 256 + threadIdx.x) * 4;
    const int i = e >> 9;
    const int j = e & (NB - 1);

    float4 sx  = *(const float4*)&g_S[0][e];
    float4 sh1 = *(const float4*)&g_S[1][e];
    float4 sh2 = *(const float4*)&g_S[2][e];
    float4 sd1 = *(const float4*)&g_S[3][e];
    float4 sd2 = *(const float4*)&g_S[4][e];
    float ni = g_invn[0][i];
    float4 nj = *(const float4*)&g_invn[1][j];

    float4 o;
    o.x = ((1.0f + sx.x) * sd1.x + (1.0f + sh1.x) * sd2.x + 1.0f + sh2.x) * ni * nj.x;
    o.y = ((1.0f + sx.y) * sd1.y + (1.0f + sh1.y) * sd2.y + 1.0f + sh2.y) * ni * nj.y;
    o.z = ((1.0f + sx.z) * sd1.z + (1.0f + sh1.z) * sd2.z + 1.0f + sh2.z) * ni * nj.z;
    o.w = ((1.0f + sx.w) * sd1.w + (1.0f + sh1.w) * sd2.w + 1.0f + sh2.w) * ni * nj.w;
    *(float4*)&out[e] = o;
}

// ===========================================================================
extern "C" void kernel_launch(void* const* d_in, const int* in_sizes, int n_in,
                              void* d_out, int out_size)
{
    const float* x1 = (const float*)d_in[0];
    const float* x2 = (const float*)d_in[1];
    const float* W1 = (const float*)d_in[2];
    const float* b1 = (const float*)d_in[3];
    const float* W2 = (const float*)d_in[4];
    const float* b2 = (const float*)d_in[5];
    const float* W3 = (const float*)d_in[6];
    float* out = (float*)d_out;

    feat_gemm<0><<<dim3(16, 4, 2), 256>>>(x1, x2, W1, b1, W2, b2, W3);
    feat_gemm<1><<<dim3(16, 4, 2), 256>>>(x1, x2, W1, b1, W2, b2, W3);
    feat_gemm<2><<<dim3(16, 4, 2), 256>>>(x1, x2, W1, b1, W2, b2, W3);
    norms_kernel<<<128, 256>>>(x1, x2);
    gram_kernel<<<dim3(8, 8, 5), 256>>>(x1, x2);
    combine_kernel<<<256, 256>>>(out);
}

// round 6
// speedup vs baseline: 1.8600x; 1.8600x over previous
#include <cuda_runtime.h>
#include <cuda_bf16.h>

#define NB    512
#define DIN   128
#define DH    256
#define COUT  0

// Scratch (fp32 features)
__device__ float g_H1[2][NB * DH];
__device__ float g_H2[2][NB * DH];
__device__ float g_D1[2][NB * DH];
__device__ float g_D2[2][NB * DH];
__device__ float g_invn[2][NB];
__device__ float g_S[5][NB * NB];   // 0:Sx 1:Sh1 2:Sh2 3:Sd1 4:Sd2

// bf16 split features, row stride 256 for all (x uses first 128 cols)
// index: 0:x 1:H1 2:H2 3:D1 4:D2
__device__ __nv_bfloat16 g_Fhi[5][2][NB * DH];
__device__ __nv_bfloat16 g_Flo[5][2][NB * DH];

// ---------------------------------------------------------------------------
__device__ __forceinline__ void split4(float4 v, __nv_bfloat16* hi,
                                       __nv_bfloat16* lo, int off) {
    float f[4] = {v.x, v.y, v.z, v.w};
    __nv_bfloat16 h[4], l[4];
#pragma unroll
    for (int c = 0; c < 4; c++) {
        h[c] = __float2bfloat16_rn(f[c]);
        l[c] = __float2bfloat16_rn(f[c] - __bfloat162float(h[c]));
    }
    __nv_bfloat162 h01{h[0], h[1]}, h23{h[2], h[3]};
    __nv_bfloat162 l01{l[0], l[1]}, l23{l[2], l[3]};
    uint2 uh, ul;
    uh.x = *(unsigned*)&h01; uh.y = *(unsigned*)&h23;
    ul.x = *(unsigned*)&l01; ul.y = *(unsigned*)&l23;
    *(uint2*)&hi[off] = uh;
    *(uint2*)&lo[off] = ul;
}

__device__ __forceinline__ void split1(float v, __nv_bfloat16* hi,
                                       __nv_bfloat16* lo, int off) {
    __nv_bfloat16 h = __float2bfloat16_rn(v);
    hi[off] = h;
    lo[off] = __float2bfloat16_rn(v - __bfloat162float(h));
}

// ===========================================================================
// Feature GEMMs (R4 scalar version, proven): 32x64 tile, KT=32, micro 2x4.
// MODE 0: H1 = relu(X @ W1 + b1); also converts X to bf16 split (y==0 CTAs)
// MODE 1: A2 = H1 @ W2 + b2 -> H2, D2
// MODE 2: D1 = mask(H1) * (D2 @ W2^T)
// ===========================================================================
template <int MODE>
__global__ void __launch_bounds__(256)
feat_gemm(const float* __restrict__ x1, const float* __restrict__ x2,
          const float* __restrict__ W1, const float* __restrict__ b1,
          const float* __restrict__ W2, const float* __restrict__ b2,
          const float* __restrict__ W3)
{
    __shared__ float As[2][32][34];
    __shared__ float Bs[2][32][68];

    const int side = blockIdx.z;
    const int i0 = blockIdx.x * 32;
    const int n0 = blockIdx.y * 64;
    const int tid = threadIdx.x;
    const int ti = tid >> 4;
    const int tj = tid & 15;

    const float* __restrict__ Ap;
    int K, lda;
    if (MODE == 0) { Ap = side ? x2 : x1; K = DIN; lda = DIN; }
    else if (MODE == 1) { Ap = g_H1[side]; K = DH; lda = DH; }
    else { Ap = g_D2[side]; K = DH; lda = DH; }

    const int ar = tid >> 3;
    const int ac4 = (tid & 7) << 2;
    const int T = K / 32;

    float4 ra, rb0, rb1;

    auto load_tiles = [&](int t) {
        int k0 = t * 32;
        ra = *(const float4*)&Ap[(i0 + ar) * lda + k0 + ac4];
        if (MODE == 2) {
            int r0 = tid >> 3, r1 = r0 + 32;
            rb0 = *(const float4*)&W2[(n0 + r0) * DH + k0 + ac4];
            rb1 = *(const float4*)&W2[(n0 + r1) * DH + k0 + ac4];
        } else {
            const float* __restrict__ Bp = (MODE == 0) ? W1 : W2;
            int kk0 = tid >> 4, j4 = (tid & 15) << 2;
            rb0 = *(const float4*)&Bp[(k0 + kk0) * DH + n0 + j4];
            rb1 = *(const float4*)&Bp[(k0 + kk0 + 16) * DH + n0 + j4];
        }
    };
    auto store_tiles = [&](int buf) {
        As[buf][ac4 + 0][ar] = ra.x;
        As[buf][ac4 + 1][ar] = ra.y;
        As[buf][ac4 + 2][ar] = ra.z;
        As[buf][ac4 + 3][ar] = ra.w;
        if (MODE == 2) {
            int r0 = tid >> 3, r1 = r0 + 32;
            Bs[buf][ac4 + 0][r0] = rb0.x; Bs[buf][ac4 + 1][r0] = rb0.y;
            Bs[buf][ac4 + 2][r0] = rb0.z; Bs[buf][ac4 + 3][r0] = rb0.w;
            Bs[buf][ac4 + 0][r1] = rb1.x; Bs[buf][ac4 + 1][r1] = rb1.y;
            Bs[buf][ac4 + 2][r1] = rb1.z; Bs[buf][ac4 + 3][r1] = rb1.w;
        } else {
            int kk0 = tid >> 4, j4 = (tid & 15) << 2;
            *(float4*)&Bs[buf][kk0][j4] = rb0;
            *(float4*)&Bs[buf][kk0 + 16][j4] = rb1;
        }
    };

    float acc[8] = {};

    load_tiles(0);
    store_tiles(0);
    __syncthreads();

    for (int t = 0; t < T; t++) {
        if (t + 1 < T) load_tiles(t + 1);
        int b = t & 1;
#pragma unroll
        for (int kk = 0; kk < 32; kk++) {
            float2 a = *(const float2*)&As[b][kk][ti * 2];
            float4 bb = *(const float4*)&Bs[b][kk][tj * 4];
            acc[0] = fmaf(a.x, bb.x, acc[0]);
            acc[1] = fmaf(a.x, bb.y, acc[1]);
            acc[2] = fmaf(a.x, bb.z, acc[2]);
            acc[3] = fmaf(a.x, bb.w, acc[3]);
            acc[4] = fmaf(a.y, bb.x, acc[4]);
            acc[5] = fmaf(a.y, bb.y, acc[5]);
            acc[6] = fmaf(a.y, bb.z, acc[6]);
            acc[7] = fmaf(a.y, bb.w, acc[7]);
        }
        if (t + 1 < T) store_tiles((t + 1) & 1);
        __syncthreads();
    }

    const int col = n0 + tj * 4;
    if (MODE == 0) {
        float4 bias = *(const float4*)&b1[col];
#pragma unroll
        for (int r = 0; r < 2; r++) {
            float4 o;
            o.x = fmaxf(acc[r * 4 + 0] + bias.x, 0.0f);
            o.y = fmaxf(acc[r * 4 + 1] + bias.y, 0.0f);
            o.z = fmaxf(acc[r * 4 + 2] + bias.z, 0.0f);
            o.w = fmaxf(acc[r * 4 + 3] + bias.w, 0.0f);
            int off = (i0 + ti * 2 + r) * DH + col;
            *(float4*)&g_H1[side][off] = o;
            split4(o, g_Fhi[1][side], g_Flo[1][side], off);
        }
        // Convert this CTA's X rows to bf16 split (one CTA column only)
        if (blockIdx.y == 0) {
            for (int e = tid; e < 32 * DIN; e += 256) {
                int r = e >> 7, cc = e & (DIN - 1);
                float v = Ap[(i0 + r) * DIN + cc];
                split1(v, g_Fhi[0][side], g_Flo[0][side], (i0 + r) * DH + cc);
            }
        }
    } else if (MODE == 1) {
        float4 bias = *(const float4*)&b2[col];
        float4 w3c;
        w3c.x = W3[(col + 0) * 10 + COUT];
        w3c.y = W3[(col + 1) * 10 + COUT];
        w3c.z = W3[(col + 2) * 10 + COUT];
        w3c.w = W3[(col + 3) * 10 + COUT];
#pragma unroll
        for (int r = 0; r < 2; r++) {
            float a0 = acc[r * 4 + 0] + bias.x;
            float a1 = acc[r * 4 + 1] + bias.y;
            float a2 = acc[r * 4 + 2] + bias.z;
            float a3 = acc[r * 4 + 3] + bias.w;
            float4 h, d;
            h.x = fmaxf(a0, 0.0f); d.x = a0 > 0.0f ? w3c.x : 0.0f;
            h.y = fmaxf(a1, 0.0f); d.y = a1 > 0.0f ? w3c.y : 0.0f;
            h.z = fmaxf(a2, 0.0f); d.z = a2 > 0.0f ? w3c.z : 0.0f;
            h.w = fmaxf(a3, 0.0f); d.w = a3 > 0.0f ? w3c.w : 0.0f;
            int off = (i0 + ti * 2 + r) * DH + col;
            *(float4*)&g_H2[side][off] = h;
            *(float4*)&g_D2[side][off] = d;
            split4(h, g_Fhi[2][side], g_Flo[2][side], off);
            split4(d, g_Fhi[4][side], g_Flo[4][side], off);
        }
    } else {
#pragma unroll
        for (int r = 0; r < 2; r++) {
            int off = (i0 + ti * 2 + r) * DH + col;
            float4 h1 = *(const float4*)&g_H1[side][off];
            float4 o;
            o.x = h1.x > 0.0f ? acc[r * 4 + 0] : 0.0f;
            o.y = h1.y > 0.0f ? acc[r * 4 + 1] : 0.0f;
            o.z = h1.z > 0.0f ? acc[r * 4 + 2] : 0.0f;
            o.w = h1.w > 0.0f ? acc[r * 4 + 3] : 0.0f;
            *(float4*)&g_D1[side][off] = o;
            split4(o, g_Fhi[3][side], g_Flo[3][side], off);
        }
    }
}

// ===========================================================================
// Tensor-core Gram kernel + folded norms (z=5).
// z<5: 64x64 tile per CTA, mma.sync m16n8k16 bf16, 3-pass hi/lo compensation.
// ===========================================================================
#define LDSM4(r, p) do { \
    unsigned _a = (unsigned)__cvta_generic_to_shared(p); \
    asm volatile("ldmatrix.sync.aligned.m8n8.x4.shared.b16 {%0,%1,%2,%3}, [%4];" \
        : "=r"((r)[0]), "=r"((r)[1]), "=r"((r)[2]), "=r"((r)[3]) : "r"(_a)); \
} while (0)

#define MMA_BF16(ac, a, b0, b1) \
    asm volatile("mma.sync.aligned.m16n8k16.row.col.f32.bf16.bf16.f32 " \
        "{%0,%1,%2,%3}, {%4,%5,%6,%7}, {%8,%9}, {%0,%1,%2,%3};" \
        : "+f"((ac)[0]), "+f"((ac)[1]), "+f"((ac)[2]), "+f"((ac)[3]) \
        : "r"((a)[0]), "r"((a)[1]), "r"((a)[2]), "r"((a)[3]), "r"(b0), "r"(b1))

__device__ __forceinline__ float sq4(float4 v) {
    return fmaf(v.x, v.x, fmaf(v.y, v.y, fmaf(v.z, v.z, v.w * v.w)));
}

__global__ void __launch_bounds__(256)
gram_mma(const float* __restrict__ x1, const float* __restrict__ x2)
{
    const int z = blockIdx.z;
    const int tid = threadIdx.x;

    if (z == 5) {
        // ---- norms: 64 CTAs, 16 samples each, half-warp per sample ----
        const int cta = blockIdx.y * 8 + blockIdx.x;
        const int warp = tid >> 5, lane = tid & 31;
        const int s = cta * 16 + warp * 2 + (lane >> 4);
        const int side = s >> 9, i = s & (NB - 1);
        const int l = lane & 15;
        const float* __restrict__ X = side ? x2 : x1;

        float sx = 0.0f;
#pragma unroll
        for (int q = 0; q < 2; q++)
            sx += sq4(*(const float4*)&X[i * DIN + (l + q * 16) * 4]);
        float sh1 = 0, sh2 = 0, sd1 = 0, sd2 = 0;
#pragma unroll
        for (int q = 0; q < 4; q++) {
            int off = i * DH + (l + q * 16) * 4;
            sh1 += sq4(*(const float4*)&g_H1[side][off]);
            sh2 += sq4(*(const float4*)&g_H2[side][off]);
            sd1 += sq4(*(const float4*)&g_D1[side][off]);
            sd2 += sq4(*(const float4*)&g_D2[side][off]);
        }
#pragma unroll
        for (int o = 8; o > 0; o >>= 1) {
            sx  += __shfl_down_sync(0xffffffffu, sx, o);
            sh1 += __shfl_down_sync(0xffffffffu, sh1, o);
            sh2 += __shfl_down_sync(0xffffffffu, sh2, o);
            sd1 += __shfl_down_sync(0xffffffffu, sd1, o);
            sd2 += __shfl_down_sync(0xffffffffu, sd2, o);
        }
        if (l == 0) {
            float n2 = (1.0f + sx) * sd1 + (1.0f + sh1) * sd2 + 1.0f + sh2;
            g_invn[side][i] = rsqrtf(n2);
        }
        return;
    }

    // ---- gram tiles ----
    __shared__ __nv_bfloat16 Ah[2][64][40], Al[2][64][40];
    __shared__ __nv_bfloat16 Bh[2][64][40], Bl[2][64][40];

    const int i0 = blockIdx.x * 64, j0 = blockIdx.y * 64;
    const int warp = tid >> 5, lane = tid & 31;
    const int K = (z == 0) ? DIN : DH;
    const int chunks = K / 32;

    const __nv_bfloat16* __restrict__ pAh = g_Fhi[z][0];
    const __nv_bfloat16* __restrict__ pAl = g_Flo[z][0];
    const __nv_bfloat16* __restrict__ pBh = g_Fhi[z][1];
    const __nv_bfloat16* __restrict__ pBl = g_Flo[z][1];

    // fill: thread -> (row, 8-col group)
    const int frow = tid >> 2;
    const int fk = (tid & 3) * 8;

    uint4 rah, ral, rbh, rbl;
    auto load_tiles = [&](int c) {
        int k0 = c * 32;
        rah = *(const uint4*)&pAh[(i0 + frow) * DH + k0 + fk];
        ral = *(const uint4*)&pAl[(i0 + frow) * DH + k0 + fk];
        rbh = *(const uint4*)&pBh[(j0 + frow) * DH + k0 + fk];
        rbl = *(const uint4*)&pBl[(j0 + frow) * DH + k0 + fk];
    };
    auto store_tiles = [&](int b) {
        *(uint4*)&Ah[b][frow][fk] = rah;
        *(uint4*)&Al[b][frow][fk] = ral;
        *(uint4*)&Bh[b][frow][fk] = rbh;
        *(uint4*)&Bl[b][frow][fk] = rbl;
    };

    // ldmatrix source coords
    const int wy = warp >> 1, wx = warp & 1;
    const int a_row = wy * 16 + ((lane >> 3) & 1) * 8 + (lane & 7);
    const int a_colb = (lane >> 4) * 8;
    const int b_row = wx * 32 + (lane >> 4) * 8 + (lane & 7);
    const int b_colb = ((lane >> 3) & 1) * 8;

    float acc[16] = {};

    load_tiles(0);
    store_tiles(0);
    __syncthreads();

    for (int c = 0; c < chunks; c++) {
        if (c + 1 < chunks) load_tiles(c + 1);
        int b = c & 1;
#pragma unroll
        for (int ks = 0; ks < 2; ks++) {
            unsigned ah[4], al[4], bh0[4], bh1[4], bl0[4], bl1[4];
            LDSM4(ah, &Ah[b][a_row][a_colb + ks * 16]);
            LDSM4(al, &Al[b][a_row][a_colb + ks * 16]);
            LDSM4(bh0, &Bh[b][b_row][b_colb + ks * 16]);
            LDSM4(bh1, &Bh[b][b_row + 16][b_colb + ks * 16]);
            LDSM4(bl0, &Bl[b][b_row][b_colb + ks * 16]);
            LDSM4(bl1, &Bl[b][b_row + 16][b_colb + ks * 16]);
            // hi*hi
            MMA_BF16(acc + 0,  ah, bh0[0], bh0[1]);
            MMA_BF16(acc + 4,  ah, bh0[2], bh0[3]);
            MMA_BF16(acc + 8,  ah, bh1[0], bh1[1]);
            MMA_BF16(acc + 12, ah, bh1[2], bh1[3]);
            // hi*lo
            MMA_BF16(acc + 0,  ah, bl0[0], bl0[1]);
            MMA_BF16(acc + 4,  ah, bl0[2], bl0[3]);
            MMA_BF16(acc + 8,  ah, bl1[0], bl1[1]);
            MMA_BF16(acc + 12, ah, bl1[2], bl1[3]);
            // lo*hi
            MMA_BF16(acc + 0,  al, bh0[0], bh0[1]);
            MMA_BF16(acc + 4,  al, bh0[2], bh0[3]);
            MMA_BF16(acc + 8,  al, bh1[0], bh1[1]);
            MMA_BF16(acc + 12, al, bh1[2], bh1[3]);
        }
        if (c + 1 < chunks) store_tiles((c + 1) & 1);
        __syncthreads();
    }

    // epilogue: c0,c1 -> (row, col..col+1); c2,c3 -> (row+8, ...)
    const int g4 = lane >> 2, tg = lane & 3;
    const int row = i0 + wy * 16 + g4;
#pragma unroll
    for (int nt = 0; nt < 4; nt++) {
        int col = j0 + wx * 32 + nt * 8 + tg * 2;
        *(float2*)&g_S[z][row * NB + col] = make_float2(acc[nt * 4 + 0], acc[nt * 4 + 1]);
        *(float2*)&g_S[z][(row + 8) * NB + col] = make_float2(acc[nt * 4 + 2], acc[nt * 4 + 3]);
    }
}

// ===========================================================================
// Elementwise combine + normalize.
// ===========================================================================
__global__ void __launch_bounds__(256)
combine_kernel(float* __restrict__ out)
{
    const int e = (blockIdx.x * 256 + threadIdx.x) * 4;
    const int i = e >> 9;
    const int j = e & (NB - 1);

    float4 sx  = *(const float4*)&g_S[0][e];
    float4 sh1 = *(const float4*)&g_S[1][e];
    float4 sh2 = *(const float4*)&g_S[2][e];
    float4 sd1 = *(const float4*)&g_S[3][e];
    float4 sd2 = *(const float4*)&g_S[4][e];
    float ni = g_invn[0][i];
    float4 nj = *(const float4*)&g_invn[1][j];

    float4 o;
    o.x = ((1.0f + sx.x) * sd1.x + (1.0f + sh1.x) * sd2.x + 1.0f + sh2.x) * ni * nj.x;
    o.y = ((1.0f + sx.y) * sd1.y + (1.0f + sh1.y) * sd2.y + 1.0f + sh2.y) * ni * nj.y;
    o.z = ((1.0f + sx.z) * sd1.z + (1.0f + sh1.z) * sd2.z + 1.0f + sh2.z) * ni * nj.z;
    o.w = ((1.0f + sx.w) * sd1.w + (1.0f + sh1.w) * sd2.w + 1.0f + sh2.w) * ni * nj.w;
    *(float4*)&out[e] = o;
}

// ===========================================================================
extern "C" void kernel_launch(void* const* d_in, const int* in_sizes, int n_in,
                              void* d_out, int out_size)
{
    const float* x1 = (const float*)d_in[0];
    const float* x2 = (const float*)d_in[1];
    const float* W1 = (const float*)d_in[2];
    const float* b1 = (const float*)d_in[3];
    const float* W2 = (const float*)d_in[4];
    const float* b2 = (const float*)d_in[5];
    const float* W3 = (const float*)d_in[6];
    float* out = (float*)d_out;

    feat_gemm<0><<<dim3(16, 4, 2), 256>>>(x1, x2, W1, b1, W2, b2, W3);
    feat_gemm<1><<<dim3(16, 4, 2), 256>>>(x1, x2, W1, b1, W2, b2, W3);
    feat_gemm<2><<<dim3(16, 4, 2), 256>>>(x1, x2, W1, b1, W2, b2, W3);
    gram_mma<<<dim3(8, 8, 6), 256>>>(x1, x2);
    combine_kernel<<<256, 256>>>(out);
}

// round 7
// speedup vs baseline: 1.8683x; 1.0045x over previous
#include <cuda_runtime.h>
#include <cuda_bf16.h>

#define NB    512
#define DIN   128
#define DH    256
#define COUT  0

// Scratch (fp32 features)
__device__ float g_H1[2][NB * DH];
__device__ float g_H2[2][NB * DH];
__device__ float g_D1[2][NB * DH];
__device__ float g_D2[2][NB * DH];
__device__ float g_invn[2][NB];
__device__ float g_S[5][NB * NB];   // 0:Sx 1:Sh1 2:Sh2 3:Sd1 4:Sd2

// bf16 split features, row stride 256 for all (x uses first 128 cols)
__device__ __nv_bfloat16 g_Fhi[5][2][NB * DH];
__device__ __nv_bfloat16 g_Flo[5][2][NB * DH];

// ---------------------------------------------------------------------------
__device__ __forceinline__ void split4(float4 v, __nv_bfloat16* hi,
                                       __nv_bfloat16* lo, int off) {
    float f[4] = {v.x, v.y, v.z, v.w};
    __nv_bfloat16 h[4], l[4];
#pragma unroll
    for (int c = 0; c < 4; c++) {
        h[c] = __float2bfloat16_rn(f[c]);
        l[c] = __float2bfloat16_rn(f[c] - __bfloat162float(h[c]));
    }
    __nv_bfloat162 h01{h[0], h[1]}, h23{h[2], h[3]};
    __nv_bfloat162 l01{l[0], l[1]}, l23{l[2], l[3]};
    uint2 uh, ul;
    uh.x = *(unsigned*)&h01; uh.y = *(unsigned*)&h23;
    ul.x = *(unsigned*)&l01; ul.y = *(unsigned*)&l23;
    *(uint2*)&hi[off] = uh;
    *(uint2*)&lo[off] = ul;
}

__device__ __forceinline__ void split1(float v, __nv_bfloat16* hi,
                                       __nv_bfloat16* lo, int off) {
    __nv_bfloat16 h = __float2bfloat16_rn(v);
    hi[off] = h;
    lo[off] = __float2bfloat16_rn(v - __bfloat162float(h));
}

// ===========================================================================
// Feature GEMMs (proven scalar): 32x64 tile, KT=32, micro 2x4.
// ===========================================================================
template <int MODE>
__global__ void __launch_bounds__(256)
feat_gemm(const float* __restrict__ x1, const float* __restrict__ x2,
          const float* __restrict__ W1, const float* __restrict__ b1,
          const float* __restrict__ W2, const float* __restrict__ b2,
          const float* __restrict__ W3)
{
    __shared__ float As[2][32][34];
    __shared__ float Bs[2][32][68];

    const int side = blockIdx.z;
    const int i0 = blockIdx.x * 32;
    const int n0 = blockIdx.y * 64;
    const int tid = threadIdx.x;
    const int ti = tid >> 4;
    const int tj = tid & 15;

    const float* __restrict__ Ap;
    int K, lda;
    if (MODE == 0) { Ap = side ? x2 : x1; K = DIN; lda = DIN; }
    else if (MODE == 1) { Ap = g_H1[side]; K = DH; lda = DH; }
    else { Ap = g_D2[side]; K = DH; lda = DH; }

    const int ar = tid >> 3;
    const int ac4 = (tid & 7) << 2;
    const int T = K / 32;

    float4 ra, rb0, rb1;

    auto load_tiles = [&](int t) {
        int k0 = t * 32;
        ra = *(const float4*)&Ap[(i0 + ar) * lda + k0 + ac4];
        if (MODE == 2) {
            int r0 = tid >> 3, r1 = r0 + 32;
            rb0 = *(const float4*)&W2[(n0 + r0) * DH + k0 + ac4];
            rb1 = *(const float4*)&W2[(n0 + r1) * DH + k0 + ac4];
        } else {
            const float* __restrict__ Bp = (MODE == 0) ? W1 : W2;
            int kk0 = tid >> 4, j4 = (tid & 15) << 2;
            rb0 = *(const float4*)&Bp[(k0 + kk0) * DH + n0 + j4];
            rb1 = *(const float4*)&Bp[(k0 + kk0 + 16) * DH + n0 + j4];
        }
    };
    auto store_tiles = [&](int buf) {
        As[buf][ac4 + 0][ar] = ra.x;
        As[buf][ac4 + 1][ar] = ra.y;
        As[buf][ac4 + 2][ar] = ra.z;
        As[buf][ac4 + 3][ar] = ra.w;
        if (MODE == 2) {
            int r0 = tid >> 3, r1 = r0 + 32;
            Bs[buf][ac4 + 0][r0] = rb0.x; Bs[buf][ac4 + 1][r0] = rb0.y;
            Bs[buf][ac4 + 2][r0] = rb0.z; Bs[buf][ac4 + 3][r0] = rb0.w;
            Bs[buf][ac4 + 0][r1] = rb1.x; Bs[buf][ac4 + 1][r1] = rb1.y;
            Bs[buf][ac4 + 2][r1] = rb1.z; Bs[buf][ac4 + 3][r1] = rb1.w;
        } else {
            int kk0 = tid >> 4, j4 = (tid & 15) << 2;
            *(float4*)&Bs[buf][kk0][j4] = rb0;
            *(float4*)&Bs[buf][kk0 + 16][j4] = rb1;
        }
    };

    float acc[8] = {};

    load_tiles(0);
    store_tiles(0);
    __syncthreads();

    for (int t = 0; t < T; t++) {
        if (t + 1 < T) load_tiles(t + 1);
        int b = t & 1;
#pragma unroll
        for (int kk = 0; kk < 32; kk++) {
            float2 a = *(const float2*)&As[b][kk][ti * 2];
            float4 bb = *(const float4*)&Bs[b][kk][tj * 4];
            acc[0] = fmaf(a.x, bb.x, acc[0]);
            acc[1] = fmaf(a.x, bb.y, acc[1]);
            acc[2] = fmaf(a.x, bb.z, acc[2]);
            acc[3] = fmaf(a.x, bb.w, acc[3]);
            acc[4] = fmaf(a.y, bb.x, acc[4]);
            acc[5] = fmaf(a.y, bb.y, acc[5]);
            acc[6] = fmaf(a.y, bb.z, acc[6]);
            acc[7] = fmaf(a.y, bb.w, acc[7]);
        }
        if (t + 1 < T) store_tiles((t + 1) & 1);
        __syncthreads();
    }

    const int col = n0 + tj * 4;
    if (MODE == 0) {
        float4 bias = *(const float4*)&b1[col];
#pragma unroll
        for (int r = 0; r < 2; r++) {
            float4 o;
            o.x = fmaxf(acc[r * 4 + 0] + bias.x, 0.0f);
            o.y = fmaxf(acc[r * 4 + 1] + bias.y, 0.0f);
            o.z = fmaxf(acc[r * 4 + 2] + bias.z, 0.0f);
            o.w = fmaxf(acc[r * 4 + 3] + bias.w, 0.0f);
            int off = (i0 + ti * 2 + r) * DH + col;
            *(float4*)&g_H1[side][off] = o;
            split4(o, g_Fhi[1][side], g_Flo[1][side], off);
        }
        if (blockIdx.y == 0) {
            for (int e = tid; e < 32 * DIN; e += 256) {
                int r = e >> 7, cc = e & (DIN - 1);
                float v = Ap[(i0 + r) * DIN + cc];
                split1(v, g_Fhi[0][side], g_Flo[0][side], (i0 + r) * DH + cc);
            }
        }
    } else if (MODE == 1) {
        float4 bias = *(const float4*)&b2[col];
        float4 w3c;
        w3c.x = W3[(col + 0) * 10 + COUT];
        w3c.y = W3[(col + 1) * 10 + COUT];
        w3c.z = W3[(col + 2) * 10 + COUT];
        w3c.w = W3[(col + 3) * 10 + COUT];
#pragma unroll
        for (int r = 0; r < 2; r++) {
            float a0 = acc[r * 4 + 0] + bias.x;
            float a1 = acc[r * 4 + 1] + bias.y;
            float a2 = acc[r * 4 + 2] + bias.z;
            float a3 = acc[r * 4 + 3] + bias.w;
            float4 h, d;
            h.x = fmaxf(a0, 0.0f); d.x = a0 > 0.0f ? w3c.x : 0.0f;
            h.y = fmaxf(a1, 0.0f); d.y = a1 > 0.0f ? w3c.y : 0.0f;
            h.z = fmaxf(a2, 0.0f); d.z = a2 > 0.0f ? w3c.z : 0.0f;
            h.w = fmaxf(a3, 0.0f); d.w = a3 > 0.0f ? w3c.w : 0.0f;
            int off = (i0 + ti * 2 + r) * DH + col;
            *(float4*)&g_H2[side][off] = h;
            *(float4*)&g_D2[side][off] = d;
            split4(h, g_Fhi[2][side], g_Flo[2][side], off);
            split4(d, g_Fhi[4][side], g_Flo[4][side], off);
        }
    } else {
#pragma unroll
        for (int r = 0; r < 2; r++) {
            int off = (i0 + ti * 2 + r) * DH + col;
            float4 h1 = *(const float4*)&g_H1[side][off];
            float4 o;
            o.x = h1.x > 0.0f ? acc[r * 4 + 0] : 0.0f;
            o.y = h1.y > 0.0f ? acc[r * 4 + 1] : 0.0f;
            o.z = h1.z > 0.0f ? acc[r * 4 + 2] : 0.0f;
            o.w = h1.w > 0.0f ? acc[r * 4 + 3] : 0.0f;
            *(float4*)&g_D1[side][off] = o;
            split4(o, g_Fhi[3][side], g_Flo[3][side], off);
        }
    }
}

// ===========================================================================
// Tensor-core Gram + folded norms. 128 threads, 4 warps of 32x32 tiles.
// ===========================================================================
#define LDSM4(r, p) do { \
    unsigned _a = (unsigned)__cvta_generic_to_shared(p); \
    asm volatile("ldmatrix.sync.aligned.m8n8.x4.shared.b16 {%0,%1,%2,%3}, [%4];" \
        : "=r"((r)[0]), "=r"((r)[1]), "=r"((r)[2]), "=r"((r)[3]) : "r"(_a)); \
} while (0)

#define MMA_BF16(ac, a, b0, b1) \
    asm volatile("mma.sync.aligned.m16n8k16.row.col.f32.bf16.bf16.f32 " \
        "{%0,%1,%2,%3}, {%4,%5,%6,%7}, {%8,%9}, {%0,%1,%2,%3};" \
        : "+f"((ac)[0]), "+f"((ac)[1]), "+f"((ac)[2]), "+f"((ac)[3]) \
        : "r"((a)[0]), "r"((a)[1]), "r"((a)[2]), "r"((a)[3]), "r"(b0), "r"(b1))

__device__ __forceinline__ float sq4(float4 v) {
    return fmaf(v.x, v.x, fmaf(v.y, v.y, fmaf(v.z, v.z, v.w * v.w)));
}

__global__ void __launch_bounds__(128)
gram_mma(const float* __restrict__ x1, const float* __restrict__ x2)
{
    const int z = blockIdx.z;
    const int tid = threadIdx.x;
    const int warp = tid >> 5, lane = tid & 31;

    if (z == 5) {
        // ---- norms: 64 CTAs x 16 samples; 8 lanes per sample ----
        const int cta = blockIdx.y * 8 + blockIdx.x;
        const int s = cta * 16 + warp * 4 + (lane >> 3);
        const int side = s >> 9, i = s & (NB - 1);
        const int l = lane & 7;
        const float* __restrict__ X = side ? x2 : x1;

        float sx = 0.0f;
#pragma unroll
        for (int q = 0; q < 4; q++)
            sx += sq4(*(const float4*)&X[i * DIN + (l + q * 8) * 4]);
        float sh1 = 0, sh2 = 0, sd1 = 0, sd2 = 0;
#pragma unroll
        for (int q = 0; q < 8; q++) {
            int off = i * DH + (l + q * 8) * 4;
            sh1 += sq4(*(const float4*)&g_H1[side][off]);
            sh2 += sq4(*(const float4*)&g_H2[side][off]);
            sd1 += sq4(*(const float4*)&g_D1[side][off]);
            sd2 += sq4(*(const float4*)&g_D2[side][off]);
        }
#pragma unroll
        for (int o = 4; o > 0; o >>= 1) {
            sx  += __shfl_down_sync(0xffffffffu, sx, o, 8);
            sh1 += __shfl_down_sync(0xffffffffu, sh1, o, 8);
            sh2 += __shfl_down_sync(0xffffffffu, sh2, o, 8);
            sd1 += __shfl_down_sync(0xffffffffu, sd1, o, 8);
            sd2 += __shfl_down_sync(0xffffffffu, sd2, o, 8);
        }
        if (l == 0) {
            float n2 = (1.0f + sx) * sd1 + (1.0f + sh1) * sd2 + 1.0f + sh2;
            g_invn[side][i] = rsqrtf(n2);
        }
        return;
    }

    // ---- gram tile 64x64, 4 warps of 32x32 ----
    __shared__ __nv_bfloat16 Ah[2][64][40], Al[2][64][40];
    __shared__ __nv_bfloat16 Bh[2][64][40], Bl[2][64][40];

    const int i0 = blockIdx.x * 64, j0 = blockIdx.y * 64;
    const int K = (z == 0) ? DIN : DH;
    const int chunks = K / 32;

    const __nv_bfloat16* __restrict__ pAh = g_Fhi[z][0];
    const __nv_bfloat16* __restrict__ pAl = g_Flo[z][0];
    const __nv_bfloat16* __restrict__ pBh = g_Fhi[z][1];
    const __nv_bfloat16* __restrict__ pBl = g_Flo[z][1];

    // fill: 2 iterations, idx = tid + q*128 -> row idx>>2, col (idx&3)*8
    uint4 rah[2], ral[2], rbh[2], rbl[2];
    auto load_tiles = [&](int c) {
        int k0 = c * 32;
#pragma unroll
        for (int q = 0; q < 2; q++) {
            int idx = tid + q * 128;
            int r = idx >> 2, ck = (idx & 3) * 8;
            rah[q] = *(const uint4*)&pAh[(i0 + r) * DH + k0 + ck];
            ral[q] = *(const uint4*)&pAl[(i0 + r) * DH + k0 + ck];
            rbh[q] = *(const uint4*)&pBh[(j0 + r) * DH + k0 + ck];
            rbl[q] = *(const uint4*)&pBl[(j0 + r) * DH + k0 + ck];
        }
    };
    auto store_tiles = [&](int b) {
#pragma unroll
        for (int q = 0; q < 2; q++) {
            int idx = tid + q * 128;
            int r = idx >> 2, ck = (idx & 3) * 8;
            *(uint4*)&Ah[b][r][ck] = rah[q];
            *(uint4*)&Al[b][r][ck] = ral[q];
            *(uint4*)&Bh[b][r][ck] = rbh[q];
            *(uint4*)&Bl[b][r][ck] = rbl[q];
        }
    };

    // warp 2x2 grid: wy rows, wx cols, each 32x32
    const int wy = warp >> 1, wx = warp & 1;
    const int a_base = wy * 32 + ((lane >> 3) & 1) * 8 + (lane & 7);
    const int a_cb = (lane >> 4) * 8;
    const int b_base = wx * 32 + (lane >> 4) * 8 + (lane & 7);
    const int b_cb = ((lane >> 3) & 1) * 8;

    float acc[2][4][4] = {};

    load_tiles(0);
    store_tiles(0);
    __syncthreads();

    for (int c = 0; c < chunks; c++) {
        if (c + 1 < chunks) load_tiles(c + 1);
        int b = c & 1;
#pragma unroll
        for (int ks = 0; ks < 2; ks++) {
            unsigned ah[2][4], al[2][4], bh[2][4], bl[2][4];
#pragma unroll
            for (int rf = 0; rf < 2; rf++) {
                LDSM4(ah[rf], &Ah[b][a_base + rf * 16][a_cb + ks * 16]);
                LDSM4(al[rf], &Al[b][a_base + rf * 16][a_cb + ks * 16]);
                LDSM4(bh[rf], &Bh[b][b_base + rf * 16][b_cb + ks * 16]);
                LDSM4(bl[rf], &Bl[b][b_base + rf * 16][b_cb + ks * 16]);
            }
#pragma unroll
            for (int rf = 0; rf < 2; rf++) {
                // hi*hi
                MMA_BF16(acc[rf][0], ah[rf], bh[0][0], bh[0][1]);
                MMA_BF16(acc[rf][1], ah[rf], bh[0][2], bh[0][3]);
                MMA_BF16(acc[rf][2], ah[rf], bh[1][0], bh[1][1]);
                MMA_BF16(acc[rf][3], ah[rf], bh[1][2], bh[1][3]);
                // hi*lo
                MMA_BF16(acc[rf][0], ah[rf], bl[0][0], bl[0][1]);
                MMA_BF16(acc[rf][1], ah[rf], bl[0][2], bl[0][3]);
                MMA_BF16(acc[rf][2], ah[rf], bl[1][0], bl[1][1]);
                MMA_BF16(acc[rf][3], ah[rf], bl[1][2], bl[1][3]);
                // lo*hi
                MMA_BF16(acc[rf][0], al[rf], bh[0][0], bh[0][1]);
                MMA_BF16(acc[rf][1], al[rf], bh[0][2], bh[0][3]);
                MMA_BF16(acc[rf][2], al[rf], bh[1][0], bh[1][1]);
                MMA_BF16(acc[rf][3], al[rf], bh[1][2], bh[1][3]);
            }
        }
        if (c + 1 < chunks) store_tiles((c + 1) & 1);
        __syncthreads();
    }

    const int g4 = lane >> 2, tg = lane & 3;
#pragma unroll
    for (int rf = 0; rf < 2; rf++) {
        int row = i0 + wy * 32 + rf * 16 + g4;
#pragma unroll
        for (int nf = 0; nf < 4; nf++) {
            int col = j0 + wx * 32 + nf * 8 + tg * 2;
            *(float2*)&g_S[z][row * NB + col] =
                make_float2(acc[rf][nf][0], acc[rf][nf][1]);
            *(float2*)&g_S[z][(row + 8) * NB + col] =
                make_float2(acc[rf][nf][2], acc[rf][nf][3]);
        }
    }
}

// ===========================================================================
// Elementwise combine + normalize.
// ===========================================================================
__global__ void __launch_bounds__(256)
combine_kernel(float* __restrict__ out)
{
    const int e = (blockIdx.x * 256 + threadIdx.x) * 4;
    const int i = e >> 9;
    const int j = e & (NB - 1);

    float4 sx  = *(const float4*)&g_S[0][e];
    float4 sh1 = *(const float4*)&g_S[1][e];
    float4 sh2 = *(const float4*)&g_S[2][e];
    float4 sd1 = *(const float4*)&g_S[3][e];
    float4 sd2 = *(const float4*)&g_S[4][e];
    float ni = g_invn[0][i];
    float4 nj = *(const float4*)&g_invn[1][j];

    float4 o;
    o.x = ((1.0f + sx.x) * sd1.x + (1.0f + sh1.x) * sd2.x + 1.0f + sh2.x) * ni * nj.x;
    o.y = ((1.0f + sx.y) * sd1.y + (1.0f + sh1.y) * sd2.y + 1.0f + sh2.y) * ni * nj.y;
    o.z = ((1.0f + sx.z) * sd1.z + (1.0f + sh1.z) * sd2.z + 1.0f + sh2.z) * ni * nj.z;
    o.w = ((1.0f + sx.w) * sd1.w + (1.0f + sh1.w) * sd2.w + 1.0f + sh2.w) * ni * nj.w;
    *(float4*)&out[e] = o;
}

// ===========================================================================
extern "C" void kernel_launch(void* const* d_in, const int* in_sizes, int n_in,
                              void* d_out, int out_size)
{
    const float* x1 = (const float*)d_in[0];
    const float* x2 = (const float*)d_in[1];
    const float* W1 = (const float*)d_in[2];
    const float* b1 = (const float*)d_in[3];
    const float* W2 = (const float*)d_in[4];
    const float* b2 = (const float*)d_in[5];
    const float* W3 = (const float*)d_in[6];
    float* out = (float*)d_out;

    feat_gemm<0><<<dim3(16, 4, 2), 256>>>(x1, x2, W1, b1, W2, b2, W3);
    feat_gemm<1><<<dim3(16, 4, 2), 256>>>(x1, x2, W1, b1, W2, b2, W3);
    feat_gemm<2><<<dim3(16, 4, 2), 256>>>(x1, x2, W1, b1, W2, b2, W3);
    gram_mma<<<dim3(8, 8, 6), 128>>>(x1, x2);
    combine_kernel<<<256, 256>>>(out);
}